// round 5
// baseline (speedup 1.0000x reference)
#include <cuda_runtime.h>
#include <cuda_fp16.h>
#include <mma.h>

using namespace nvcuda;

#define NN 50000
#define NE 1600000
#define CD 128      // HEADS * OUT_F
#define HEADS 4
#define NCH 391     // ceil(NN/128)

// ---------------- device-global scratch (no allocations allowed) ------------
__device__ __half g_h16[(size_t)NN * CD];   // 12.8 MB (fp16 features)
__device__ float  g_esrc[NN * HEADS];
__device__ float  g_edst[NN * HEADS];
__device__ int    g_deg[NN];
__device__ int    g_off[NN + 1];
__device__ int    g_cursor[NN];
__device__ int    g_ecol[NE];
__device__ int    g_part[NCH];
__device__ int    g_base[NCH];
__device__ int    g_is64;

// ---------------- static host resources --------------------------------------
static cudaStream_t s_side = 0;
static cudaEvent_t  s_fork = 0, s_join = 0;
namespace {
struct StreamInit {
    StreamInit() {
        cudaStreamCreateWithFlags(&s_side, cudaStreamNonBlocking);
        cudaEventCreateWithFlags(&s_fork, cudaEventDisableTiming);
        cudaEventCreateWithFlags(&s_join, cudaEventDisableTiming);
    }
};
StreamInit s_init_;
}

// ---------------- detect index dtype ----------------------------------------
__global__ void k_detect(const int* __restrict__ idx32) {
    __shared__ int cnt;
    if (threadIdx.x == 0) cnt = 0;
    __syncthreads();
    int v = idx32[2 * threadIdx.x + 1];
    unsigned m = __ballot_sync(0xffffffffu, v == 0);
    if ((threadIdx.x & 31) == 0) atomicAdd(&cnt, __popc(m));
    __syncthreads();
    if (threadIdx.x == 0) g_is64 = (cnt > 128) ? 1 : 0;
}

// ---------------- tf32 tensor-core GEMM + logits -----------------------------
// 128 threads (4 warps). Block tile 64 rows x 128 cols, K=128 in 4 chunks of 32.
// smem union: mainloop  [xs 64x32 | Ws 32x128] = 24KB inside 32KB
//             epilogue  4 warps x (16x128 f32) = 32KB
__global__ __launch_bounds__(128) void k_gemm(const float* __restrict__ x,
                                              const float* __restrict__ W,
                                              const float* __restrict__ att) {
    __shared__ float sm[8192];                 // 32 KB
    float* xs = sm;                            // 64*32 = 2048 floats
    float* Ws = sm + 2048;                     // 32*128 = 4096 floats

    const int t = threadIdx.x;
    const int w = t >> 5, lane = t & 31;
    const int R0 = blockIdx.x * 64;

    wmma::fragment<wmma::accumulator, 16, 16, 8, float> acc[8];
#pragma unroll
    for (int c = 0; c < 8; c++) wmma::fill_fragment(acc[c], 0.f);

    for (int kc = 0; kc < 4; kc++) {
        __syncthreads();
        // x tile: 64 rows x 32 cols -> 512 float4, 4 per thread
#pragma unroll
        for (int j = 0; j < 4; j++) {
            int i = t + 128 * j;               // float4 index
            int row = i >> 3, kq = i & 7;
            int n = R0 + row;
            float4 v = (n < NN) ? __ldg((const float4*)&x[(size_t)n * CD + kc * 32 + kq * 4])
                                : make_float4(0.f, 0.f, 0.f, 0.f);
            *(float4*)&xs[row * 32 + kq * 4] = v;
        }
        // W tile: 32 rows x 128 cols -> 1024 float4, 8 per thread
#pragma unroll
        for (int j = 0; j < 8; j++) {
            int i = t + 128 * j;
            int kr = i >> 5, c4 = i & 31;
            *(float4*)&Ws[kr * 128 + c4 * 4] =
                __ldg((const float4*)&W[(size_t)(kc * 32 + kr) * CD + c4 * 4]);
        }
        __syncthreads();

#pragma unroll
        for (int k0 = 0; k0 < 32; k0 += 8) {
            wmma::fragment<wmma::matrix_a, 16, 16, 8, wmma::precision::tf32, wmma::row_major> af;
            wmma::load_matrix_sync(af, &xs[w * 16 * 32 + k0], 32);
#pragma unroll
            for (int i = 0; i < af.num_elements; i++)
                af.x[i] = wmma::__float_to_tf32(af.x[i]);
#pragma unroll
            for (int c = 0; c < 8; c++) {
                wmma::fragment<wmma::matrix_b, 16, 16, 8, wmma::precision::tf32, wmma::row_major> bf;
                wmma::load_matrix_sync(bf, &Ws[k0 * 128 + c * 16], 128);
#pragma unroll
                for (int i = 0; i < bf.num_elements; i++)
                    bf.x[i] = wmma::__float_to_tf32(bf.x[i]);
                wmma::mma_sync(acc[c], af, bf, acc[c]);
            }
        }
    }

    // epilogue: each warp dumps its 16x128 block to its own smem region
    __syncthreads();
    float* ep = sm + w * 2048;                 // 16 x 128
#pragma unroll
    for (int c = 0; c < 8; c++)
        wmma::store_matrix_sync(&ep[c * 16], acc[c], 128, wmma::mem_row_major);
    __syncwarp();

    // fp16 h rows: per row 32 uint2 (4 halfs each); lane l -> uint2 l
#pragma unroll
    for (int rr = 0; rr < 16; rr++) {
        int n = R0 + w * 16 + rr;
        if (n >= NN) break;
        const float* rowp = &ep[rr * 128 + lane * 4];
        __half2 h0 = __floats2half2_rn(rowp[0], rowp[1]);
        __half2 h1 = __floats2half2_rn(rowp[2], rowp[3]);
        uint2 pk;
        pk.x = *(const unsigned*)&h0;
        pk.y = *(const unsigned*)&h1;
        ((uint2*)&g_h16[(size_t)n * CD])[lane] = pk;
    }
    // logits: 64 (row,head) pairs -> 2 per lane
#pragma unroll
    for (int q = 0; q < 2; q++) {
        int p = lane + 32 * q;
        int rr = p >> 2, hd = p & 3;
        int n = R0 + w * 16 + rr;
        if (n >= NN) continue;
        const float* rowp = &ep[rr * 128 + hd * 32];
        float es = 0.f, ed = 0.f;
#pragma unroll
        for (int c = 0; c < 32; c++) {
            float v = rowp[c];
            es += v * __ldg(&att[hd * 64 + c]);
            ed += v * __ldg(&att[hd * 64 + 32 + c]);
        }
        g_esrc[n * HEADS + hd] = es;
        g_edst[n * HEADS + hd] = ed;
    }
}

// ---------------- CSR: degree count (8 edges/thread) -------------------------
__global__ void k_deg(const int* __restrict__ idx32) {
    int base = 8 * (blockIdx.x * blockDim.x + threadIdx.x);
    if (base >= NE) return;
    int r[8];
    if (g_is64) {
        const int4* p = (const int4*)&idx32[2 * base];
        int4 a = __ldg(p), b = __ldg(p + 1), c = __ldg(p + 2), d = __ldg(p + 3);
        r[0] = a.x; r[1] = a.z; r[2] = b.x; r[3] = b.z;
        r[4] = c.x; r[5] = c.z; r[6] = d.x; r[7] = d.z;
    } else {
        const int4* p = (const int4*)&idx32[base];
        int4 a = __ldg(p), b = __ldg(p + 1);
        r[0] = a.x; r[1] = a.y; r[2] = a.z; r[3] = a.w;
        r[4] = b.x; r[5] = b.y; r[6] = b.z; r[7] = b.w;
    }
#pragma unroll
    for (int j = 0; j < 8; j++)
        if ((unsigned)r[j] < (unsigned)NN) atomicAdd(&g_deg[r[j]], 1);
}

// ---------------- CSR: 3-stage multi-block exclusive scan --------------------
__global__ void k_part() {
    int j = blockIdx.x * 128 + threadIdx.x;
    int v = (j < NN) ? g_deg[j] : 0;
    int lane = threadIdx.x & 31, w = threadIdx.x >> 5;
#pragma unroll
    for (int o = 16; o > 0; o >>= 1) v += __shfl_down_sync(0xffffffffu, v, o);
    __shared__ int ws[4];
    if (lane == 0) ws[w] = v;
    __syncthreads();
    if (threadIdx.x == 0) g_part[blockIdx.x] = ws[0] + ws[1] + ws[2] + ws[3];
}

__global__ void k_mid() {
    const int t = threadIdx.x;                 // 512 threads
    int v = (t < NCH) ? g_part[t] : 0;
    int lane = t & 31, w = t >> 5;
    int inc = v;
#pragma unroll
    for (int o = 1; o < 32; o <<= 1) {
        int u = __shfl_up_sync(0xffffffffu, inc, o);
        if (lane >= o) inc += u;
    }
    __shared__ int ws[16];
    if (lane == 31) ws[w] = inc;
    __syncthreads();
    if (t == 0) {
        int run = 0;
#pragma unroll
        for (int i = 0; i < 16; i++) { int xx = ws[i]; ws[i] = run; run += xx; }
    }
    __syncthreads();
    int excl = inc - v + ws[w];
    if (t < NCH) g_base[t] = excl;
    if (t == NCH - 1) g_off[NN] = excl + v;
}

__global__ void k_out() {
    const int b = blockIdx.x, t = threadIdx.x; // 128 threads
    int j = b * 128 + t;
    int v = (j < NN) ? g_deg[j] : 0;
    int lane = t & 31, w = t >> 5;
    int inc = v;
#pragma unroll
    for (int o = 1; o < 32; o <<= 1) {
        int u = __shfl_up_sync(0xffffffffu, inc, o);
        if (lane >= o) inc += u;
    }
    __shared__ int ws[4];
    if (lane == 31) ws[w] = inc;
    __syncthreads();
    if (t == 0) {
        int run = 0;
#pragma unroll
        for (int i = 0; i < 4; i++) { int xx = ws[i]; ws[i] = run; run += xx; }
    }
    __syncthreads();
    int off = g_base[b] + ws[w] + inc - v;
    if (j < NN) { g_off[j] = off; g_cursor[j] = off; }
}

// ---------------- CSR: scatter (4 edges/thread) ------------------------------
__global__ void k_fill(const int* __restrict__ idx32) {
    int base = 4 * (blockIdx.x * blockDim.x + threadIdx.x);
    if (base >= NE) return;
    int r[4], c[4];
    if (g_is64) {
        const int4* rp = (const int4*)&idx32[2 * base];
        const int4* cp = (const int4*)&idx32[2 * (NE + base)];
        int4 a = __ldg(rp), b = __ldg(rp + 1);
        int4 e = __ldg(cp), f = __ldg(cp + 1);
        r[0] = a.x; r[1] = a.z; r[2] = b.x; r[3] = b.z;
        c[0] = e.x; c[1] = e.z; c[2] = f.x; c[3] = f.z;
    } else {
        int4 a = __ldg((const int4*)&idx32[base]);
        int4 e = __ldg((const int4*)&idx32[NE + base]);
        r[0] = a.x; r[1] = a.y; r[2] = a.z; r[3] = a.w;
        c[0] = e.x; c[1] = e.y; c[2] = e.z; c[3] = e.w;
    }
#pragma unroll
    for (int j = 0; j < 4; j++) {
        if ((unsigned)r[j] < (unsigned)NN && (unsigned)c[j] < (unsigned)NN) {
            int p = atomicAdd(&g_cursor[r[j]], 1);
            g_ecol[p] = c[j];
        }
    }
}

// ---------------- aggregate: warp/node, lane owns 4 contiguous features -----
__global__ void k_agg(const float* __restrict__ bias, float* __restrict__ out) {
    const int gw = (blockIdx.x * blockDim.x + threadIdx.x) >> 5;
    const int lane = threadIdx.x & 31;
    if (gw >= NN) return;
    const int hd = lane >> 3;
    const int e0 = g_off[gw], e1 = g_off[gw + 1];
    const float es = __ldg(&g_esrc[gw * HEADS + hd]);

    float a0 = 0.f, a1 = 0.f, a2 = 0.f, a3 = 0.f, d = 0.f;
    const uint2* __restrict__ hb = (const uint2*)g_h16;

#pragma unroll 2
    for (int e = e0; e < e1; e++) {
        int c = __ldg(&g_ecol[e]);                       // warp-broadcast
        float ed = __ldg(&g_edst[c * HEADS + hd]);
        float z = es + ed;
        z = fmaxf(z, 0.2f * z);                          // exact leaky relu
        z = __expf(z);
        uint2 hv = __ldg(&hb[(size_t)c * 32 + lane]);    // LDG.64 coalesced
        float2 f0 = __half22float2(*(const __half2*)&hv.x);
        float2 f1 = __half22float2(*(const __half2*)&hv.y);
        a0 += z * f0.x; a1 += z * f0.y;
        a2 += z * f1.x; a3 += z * f1.y;
        d  += z;
    }

    float inv = 1.f / (d + 1e-16f);
    float4 b4 = __ldg((const float4*)&bias[4 * lane]);
    float4 o;
    o.x = a0 * inv + b4.x;
    o.y = a1 * inv + b4.y;
    o.z = a2 * inv + b4.z;
    o.w = a3 * inv + b4.w;
    ((float4*)out)[(size_t)gw * 32 + lane] = o;
}

// ---------------- launch: CSR chain (side) || tensor GEMM (main) -------------
extern "C" void kernel_launch(void* const* d_in, const int* in_sizes, int n_in,
                              void* d_out, int out_size) {
    const float* x    = (const float*)d_in[0];
    const int*   idx  = (const int*)d_in[1];
    const float* W    = (const float*)d_in[2];
    const float* att  = (const float*)d_in[3];
    const float* bias = (const float*)d_in[4];
    float*       out  = (float*)d_out;

    void* degp = 0;
    cudaGetSymbolAddress(&degp, g_deg);

    const bool forked = (s_side != 0 && s_fork != 0 && s_join != 0);
    cudaStream_t cs = forked ? s_side : (cudaStream_t)0;

    if (forked) {
        cudaEventRecord(s_fork, 0);
        cudaStreamWaitEvent(s_side, s_fork, 0);
    }
    // CSR chain, entirely on side stream
    k_detect<<<1, 256, 0, cs>>>(idx);
    cudaMemsetAsync(degp, 0, NN * sizeof(int), cs);
    k_deg <<<(NE / 8 + 255) / 256, 256, 0, cs>>>(idx);
    k_part<<<NCH, 128, 0, cs>>>();
    k_mid <<<1, 512, 0, cs>>>();
    k_out <<<NCH, 128, 0, cs>>>();
    k_fill<<<(NE / 4 + 255) / 256, 256, 0, cs>>>(idx);
    if (forked) cudaEventRecord(s_join, s_side);

    // tensor-core GEMM on main stream, starts immediately
    k_gemm<<<(NN + 63) / 64, 128>>>(x, W, att);

    if (forked) cudaStreamWaitEvent((cudaStream_t)0, s_join, 0);
    k_agg<<<(NN * 32 + 255) / 256, 256>>>(bias, out);
}